// round 15
// baseline (speedup 1.0000x reference)
#include <cuda_runtime.h>
#include <math.h>

// Problem constants (fixed shapes for this problem)
#define NMAX 100000
#define EMAX 3200000
#define SCAN_B 1024

// ---------------- scratch (device globals; no allocation allowed) ------------
__device__ int    g_deg[NMAX];                       // in-degree (int)
__device__ int    g_off[NMAX];                       // CSR exclusive offsets
__device__ int    g_rank[EMAX];                      // edge rank within its dst
__device__ int    g_csr_src[EMAX];                   // src ids, grouped by dst
__device__ int    g_blocksum[128];                   // scan partials
__device__ float  g_dinv[NMAX];                      // rsqrt(deg+1)
// Double-buffered bf16 message arrays (gather input vs GEMM output must be
// distinct buffers: cross-block race otherwise).
__device__ uint4  g_msgA[(size_t)NMAX * 8];          // 8 uint4 = 64 bf16 / node
__device__ uint4  g_msgB[(size_t)NMAX * 8];
__device__ float  g_partial[16384];                  // pooling partials

// ---------------- packed helpers ---------------------------------------------
__device__ __forceinline__ unsigned long long pack_f32x2(float lo, float hi) {
    unsigned long long r;
    asm("mov.b64 %0, {%1, %2};" : "=l"(r) : "f"(lo), "f"(hi));
    return r;
}
__device__ __forceinline__ void fma_f32x2(unsigned long long& d,
                                          unsigned long long a,
                                          unsigned long long b) {
    asm("fma.rn.f32x2 %0, %1, %2, %0;" : "+l"(d) : "l"(a), "l"(b));
}
__device__ __forceinline__ void unpack_f32x2(float& lo, float& hi, unsigned long long v) {
    asm("mov.b64 {%0, %1}, %2;" : "=f"(lo), "=f"(hi) : "l"(v));
}
__device__ __forceinline__ unsigned cvt_bf16x2(float lo, float hi) {
    unsigned r;
    asm("cvt.rn.bf16x2.f32 %0, %1, %2;" : "=r"(r) : "f"(hi), "f"(lo));
    return r;
}
__device__ __forceinline__ void add_bf2(float& a, float& b, unsigned p) {
    a += __uint_as_float(p << 16);
    b += __uint_as_float(p & 0xffff0000u);
}

// ---------------- degree / CSR construction ----------------------------------
// Counts in-degree AND captures each edge's arrival rank within its dst.
__global__ void deg_count_kernel(const int* __restrict__ ei, int E) {
    int e = (blockIdx.x * 256 + threadIdx.x) * 2;
    if (e + 1 < E) {
        int2 d2 = *(const int2*)&ei[E + e];
        g_rank[e]     = atomicAdd(&g_deg[d2.x], 1);
        g_rank[e + 1] = atomicAdd(&g_deg[d2.y], 1);
    } else if (e < E) {
        g_rank[e] = atomicAdd(&g_deg[ei[E + e]], 1);
    }
}

// Shuffle-based block exclusive scan of g_deg -> g_off (+ dinv fold-in).
__global__ void scan1_kernel(int n) {
    __shared__ int warpsum[32];
    int i = blockIdx.x * SCAN_B + threadIdx.x;
    int v = (i < n) ? g_deg[i] : 0;
    if (i < n) g_dinv[i] = rsqrtf((float)v + 1.0f);
    int lane = threadIdx.x & 31;
    int wid = threadIdx.x >> 5;
    int x = v;
#pragma unroll
    for (int off = 1; off < 32; off <<= 1) {
        int y = __shfl_up_sync(0xffffffffu, x, off);
        if (lane >= off) x += y;
    }
    if (lane == 31) warpsum[wid] = x;
    __syncthreads();
    if (wid == 0) {
        int s = warpsum[lane];
#pragma unroll
        for (int off = 1; off < 32; off <<= 1) {
            int y = __shfl_up_sync(0xffffffffu, s, off);
            if (lane >= off) s += y;
        }
        warpsum[lane] = s;
    }
    __syncthreads();
    int base = (wid > 0) ? warpsum[wid - 1] : 0;
    int incl = base + x;
    if (i < n) g_off[i] = incl - v;                  // exclusive within block
    if (threadIdx.x == SCAN_B - 1) g_blocksum[blockIdx.x] = incl;
}

// Merged scan2+scan3: every block redundantly scans the <=128 block totals.
__global__ void scan23_kernel(int n, int nb) {
    __shared__ int ws[4];
    __shared__ int incl128[128];
    int t = threadIdx.x;
    if (t < 128) {
        int lane = t & 31;
        int w = t >> 5;
        int s = (t < nb) ? g_blocksum[t] : 0;
#pragma unroll
        for (int off = 1; off < 32; off <<= 1) {
            int y = __shfl_up_sync(0xffffffffu, s, off);
            if (lane >= off) s += y;
        }
        if (lane == 31) ws[w] = s;
        incl128[t] = s;
    }
    __syncthreads();
    if (t < 128) {
        int w = t >> 5;
        int add = 0;
        for (int u = 0; u < w; u++) add += ws[u];
        incl128[t] += add;
    }
    __syncthreads();
    int add = (blockIdx.x == 0) ? 0 : incl128[blockIdx.x - 1];
    int i = blockIdx.x * SCAN_B + t;
    if (i < n) g_off[i] += add;
}

// Atomic-free CSR fill: pos = off[dst] + rank (captured during counting).
__global__ void csr_fill_kernel(const int* __restrict__ ei, int E) {
    int e = (blockIdx.x * 256 + threadIdx.x) * 2;
    if (e + 1 < E) {
        int2 s2 = *(const int2*)&ei[e];
        int2 d2 = *(const int2*)&ei[E + e];
        int2 r2 = *(const int2*)&g_rank[e];
        g_csr_src[g_off[d2.x] + r2.x] = s2.x;
        g_csr_src[g_off[d2.y] + r2.y] = s2.y;
    } else if (e < E) {
        g_csr_src[g_off[ei[E + e]] + g_rank[e]] = ei[e];
    }
}

// ---------------- layer-1 GEMM: tiled, 2 nodes/thread -------------------------
// msgA[node,:] = bf16((X[node,:] @ W) * dinv[node])
__global__ void __launch_bounds__(128)
gemm_scaled_kernel(const float* __restrict__ X, const float* __restrict__ W, int n) {
    constexpr int K = 256, NOUT = 64, KC = 32, TS = 33;
    __shared__ float Xs[256 * TS];                  // 33.8 KB
    __shared__ alignas(16) float Wsh[KC * NOUT];    // 8 KB

    const float4* X4 = (const float4*)X;
    int t = threadIdx.x;
    int base = blockIdx.x * 256;
    int n0 = base + t, n1 = base + t + 128;
    bool v0 = n0 < n, v1 = n1 < n;

    unsigned long long acc0[NOUT / 2], acc1[NOUT / 2];
#pragma unroll
    for (int j = 0; j < NOUT / 2; j++) { acc0[j] = 0ull; acc1[j] = 0ull; }

    for (int k0 = 0; k0 < K; k0 += KC) {
        __syncthreads();
        for (int i = t; i < KC * NOUT; i += 128)
            Wsh[i] = W[k0 * NOUT + i];
        for (int f = t; f < 256 * (KC / 4); f += 128) {
            int row = f >> 3;
            int c4 = f & 7;
            float4 val = make_float4(0.f, 0.f, 0.f, 0.f);
            if (base + row < n)
                val = X4[(size_t)(base + row) * (K / 4) + k0 / 4 + c4];
            float* dst = &Xs[row * TS + c4 * 4];
            dst[0] = val.x; dst[1] = val.y; dst[2] = val.z; dst[3] = val.w;
        }
        __syncthreads();

        for (int kk = 0; kk < KC; kk++) {
            float x0 = Xs[t * TS + kk];
            float x1 = Xs[(t + 128) * TS + kk];
            unsigned long long p0 = pack_f32x2(x0, x0);
            unsigned long long p1 = pack_f32x2(x1, x1);
            const ulonglong2* wrow2 = (const ulonglong2*)&Wsh[kk * NOUT];
#pragma unroll
            for (int j = 0; j < NOUT / 4; j++) {
                ulonglong2 w = wrow2[j];
                fma_f32x2(acc0[2 * j + 0], p0, w.x);
                fma_f32x2(acc0[2 * j + 1], p0, w.y);
                fma_f32x2(acc1[2 * j + 0], p1, w.x);
                fma_f32x2(acc1[2 * j + 1], p1, w.y);
            }
        }
    }

    if (v0) {
        float dv = g_dinv[n0];
#pragma unroll
        for (int q = 0; q < NOUT / 8; q++) {
            unsigned r[4];
#pragma unroll
            for (int u = 0; u < 4; u++) {
                float lo, hi;
                unpack_f32x2(lo, hi, acc0[4 * q + u]);
                r[u] = cvt_bf16x2(lo * dv, hi * dv);
            }
            g_msgA[(size_t)n0 * 8 + q] = make_uint4(r[0], r[1], r[2], r[3]);
        }
    }
    if (v1) {
        float dv = g_dinv[n1];
#pragma unroll
        for (int q = 0; q < NOUT / 8; q++) {
            unsigned r[4];
#pragma unroll
            for (int u = 0; u < 4; u++) {
                float lo, hi;
                unpack_f32x2(lo, hi, acc1[4 * q + u]);
                r[u] = cvt_bf16x2(lo * dv, hi * dv);
            }
            g_msgA[(size_t)n1 * 8 + q] = make_uint4(r[0], r[1], r[2], r[3]);
        }
    }
}

// ---------------- fused aggregate + next-layer GEMM (warp-autonomous) ---------
// Gather loop is software-pipelined: next iteration's 8 CSR indices are
// prefetched before this iteration's 8 row gathers issue, breaking the
// serial idx->gather dependency chain (~250cyc each, L2-resident data).
// dir=0: in=msgA out=msgB ; dir=1: in=msgB out=msgA
template <int NIN, int NOUT>
__global__ void fused_agg_gemm_kernel(const float* __restrict__ bias,
                                      const float* __restrict__ W,
                                      int n, int dir) {
    constexpr int CH = NIN / 8;                  // lanes per node (agg phase)
    constexpr int NPB = 256 / CH;                // nodes per block
    constexpr int HS = NIN + 4;                  // padded h row (floats)
    __shared__ alignas(16) float Wsh[NIN * NOUT];
    __shared__ alignas(16) float Hsh[NPB * HS];

    const uint4* __restrict__ msg_in  = dir ? g_msgB : g_msgA;
    uint2* __restrict__       msg_out = dir ? (uint2*)g_msgA : (uint2*)g_msgB;

    int lnode = threadIdx.x / CH;
    int c = threadIdx.x % CH;
    int node = blockIdx.x * NPB + lnode;
    bool valid = node < n;

    for (int i = threadIdx.x; i < NIN * NOUT; i += 256) Wsh[i] = W[i];
    __syncthreads();   // Wsh ready BEFORE divergent gather; no barrier after

    float acc[8];
#pragma unroll
    for (int u = 0; u < 8; u++) acc[u] = 0.0f;

    if (valid) {
        int start = g_off[node];
        int end = start + g_deg[node];
        {
            uint4 sv = msg_in[(size_t)node * CH + c];   // self-loop
            add_bf2(acc[0], acc[1], sv.x);
            add_bf2(acc[2], acc[3], sv.y);
            add_bf2(acc[4], acc[5], sv.z);
            add_bf2(acc[6], acc[7], sv.w);
        }
        int nfull = (end - start) >> 3;
        int sidx[8];
        if (nfull > 0) {
#pragma unroll
            for (int u = 0; u < 8; u++) sidx[u] = g_csr_src[start + u];
        }
        for (int it = 0; it < nfull; it++) {
            int nidx[8];
            if (it + 1 < nfull) {
                int eb = start + (it + 1) * 8;
#pragma unroll
                for (int u = 0; u < 8; u++) nidx[u] = g_csr_src[eb + u];
            }
            uint4 v[8];
#pragma unroll
            for (int u = 0; u < 8; u++) v[u] = msg_in[(size_t)sidx[u] * CH + c];
#pragma unroll
            for (int u = 0; u < 8; u++) {
                add_bf2(acc[0], acc[1], v[u].x);
                add_bf2(acc[2], acc[3], v[u].y);
                add_bf2(acc[4], acc[5], v[u].z);
                add_bf2(acc[6], acc[7], v[u].w);
            }
            if (it + 1 < nfull) {
#pragma unroll
                for (int u = 0; u < 8; u++) sidx[u] = nidx[u];
            }
        }
        for (int e = start + nfull * 8; e < end; e++) {
            uint4 v = msg_in[(size_t)g_csr_src[e] * CH + c];
            add_bf2(acc[0], acc[1], v.x);
            add_bf2(acc[2], acc[3], v.y);
            add_bf2(acc[4], acc[5], v.z);
            add_bf2(acc[6], acc[7], v.w);
        }
        float dv = g_dinv[node];
        const float4* b4 = (const float4*)bias;
        float4 bl = b4[c * 2 + 0];
        float4 bh = b4[c * 2 + 1];
        acc[0] = fmaxf(fmaf(dv, acc[0], bl.x), 0.0f);
        acc[1] = fmaxf(fmaf(dv, acc[1], bl.y), 0.0f);
        acc[2] = fmaxf(fmaf(dv, acc[2], bl.z), 0.0f);
        acc[3] = fmaxf(fmaf(dv, acc[3], bl.w), 0.0f);
        acc[4] = fmaxf(fmaf(dv, acc[4], bh.x), 0.0f);
        acc[5] = fmaxf(fmaf(dv, acc[5], bh.y), 0.0f);
        acc[6] = fmaxf(fmaf(dv, acc[6], bh.z), 0.0f);
        acc[7] = fmaxf(fmaf(dv, acc[7], bh.w), 0.0f);
    }
    float* hrow = &Hsh[lnode * HS];
    *(float4*)&hrow[c * 8 + 0] = make_float4(acc[0], acc[1], acc[2], acc[3]);
    *(float4*)&hrow[c * 8 + 4] = make_float4(acc[4], acc[5], acc[6], acc[7]);
    __syncwarp();      // h rows for this warp's nodes are warp-local

    if (valid) {
        unsigned long long a0 = 0ull, a1 = 0ull;         // outputs c*4..c*4+3
#pragma unroll
        for (int k = 0; k < NIN; k += 4) {
            float4 x4 = *(const float4*)&hrow[k];
            float xs[4] = {x4.x, x4.y, x4.z, x4.w};
#pragma unroll
            for (int t = 0; t < 4; t++) {
                unsigned long long x2 = pack_f32x2(xs[t], xs[t]);
                ulonglong2 w = *(const ulonglong2*)&Wsh[(k + t) * NOUT + c * 4];
                fma_f32x2(a0, x2, w.x);
                fma_f32x2(a1, x2, w.y);
            }
        }
        float dv = g_dinv[node];
        float o0, o1, o2, o3;
        unpack_f32x2(o0, o1, a0);
        unpack_f32x2(o2, o3, a1);
        uint2 pk;
        pk.x = cvt_bf16x2(o0 * dv, o1 * dv);
        pk.y = cvt_bf16x2(o2 * dv, o3 * dv);
        msg_out[(size_t)node * (NOUT / 4) + c] = pk;
    }
}

// ---------------- fused aggregate (16 feats) + block pooling ------------------
__global__ void fused_agg_pool_kernel(const float* __restrict__ bias, int n) {
    constexpr int CH = 2, NPB = 128, HS = 16;
    __shared__ float Hsh[NPB * HS];
    __shared__ float s[256];

    int lnode = threadIdx.x / CH;
    int c = threadIdx.x % CH;
    int node = blockIdx.x * NPB + lnode;
    bool valid = node < n;

    float acc[8];
#pragma unroll
    for (int u = 0; u < 8; u++) acc[u] = 0.0f;

    if (valid) {
        int start = g_off[node];
        int end = start + g_deg[node];
        {
            uint4 sv = g_msgA[(size_t)node * CH + c];
            add_bf2(acc[0], acc[1], sv.x);
            add_bf2(acc[2], acc[3], sv.y);
            add_bf2(acc[4], acc[5], sv.z);
            add_bf2(acc[6], acc[7], sv.w);
        }
        int nfull = (end - start) >> 3;
        int sidx[8];
        if (nfull > 0) {
#pragma unroll
            for (int u = 0; u < 8; u++) sidx[u] = g_csr_src[start + u];
        }
        for (int it = 0; it < nfull; it++) {
            int nidx[8];
            if (it + 1 < nfull) {
                int eb = start + (it + 1) * 8;
#pragma unroll
                for (int u = 0; u < 8; u++) nidx[u] = g_csr_src[eb + u];
            }
            uint4 v[8];
#pragma unroll
            for (int u = 0; u < 8; u++) v[u] = g_msgA[(size_t)sidx[u] * CH + c];
#pragma unroll
            for (int u = 0; u < 8; u++) {
                add_bf2(acc[0], acc[1], v[u].x);
                add_bf2(acc[2], acc[3], v[u].y);
                add_bf2(acc[4], acc[5], v[u].z);
                add_bf2(acc[6], acc[7], v[u].w);
            }
            if (it + 1 < nfull) {
#pragma unroll
                for (int u = 0; u < 8; u++) sidx[u] = nidx[u];
            }
        }
        for (int e = start + nfull * 8; e < end; e++) {
            uint4 v = g_msgA[(size_t)g_csr_src[e] * CH + c];
            add_bf2(acc[0], acc[1], v.x);
            add_bf2(acc[2], acc[3], v.y);
            add_bf2(acc[4], acc[5], v.z);
            add_bf2(acc[6], acc[7], v.w);
        }
        float dv = g_dinv[node];
        const float4* b4 = (const float4*)bias;
        float4 bl = b4[c * 2 + 0];
        float4 bh = b4[c * 2 + 1];
        acc[0] = fmaxf(fmaf(dv, acc[0], bl.x), 0.0f);
        acc[1] = fmaxf(fmaf(dv, acc[1], bl.y), 0.0f);
        acc[2] = fmaxf(fmaf(dv, acc[2], bl.z), 0.0f);
        acc[3] = fmaxf(fmaf(dv, acc[3], bl.w), 0.0f);
        acc[4] = fmaxf(fmaf(dv, acc[4], bh.x), 0.0f);
        acc[5] = fmaxf(fmaf(dv, acc[5], bh.y), 0.0f);
        acc[6] = fmaxf(fmaf(dv, acc[6], bh.z), 0.0f);
        acc[7] = fmaxf(fmaf(dv, acc[7], bh.w), 0.0f);
    }
    float* hrow = &Hsh[lnode * HS];
    *(float4*)&hrow[c * 8 + 0] = make_float4(acc[0], acc[1], acc[2], acc[3]);
    *(float4*)&hrow[c * 8 + 4] = make_float4(acc[4], acc[5], acc[6], acc[7]);
    __syncthreads();

    int f = threadIdx.x & 15;
    int grp = threadIdx.x >> 4;
    float sum = 0.0f;
#pragma unroll
    for (int u = 0; u < 8; u++)
        sum += Hsh[(grp + u * 16) * HS + f];
    s[threadIdx.x] = sum;
    __syncthreads();
    for (int off = 128; off >= 16; off >>= 1) {
        if (threadIdx.x < off) s[threadIdx.x] += s[threadIdx.x + off];
        __syncthreads();
    }
    if (threadIdx.x < 16) g_partial[blockIdx.x * 16 + threadIdx.x] = s[threadIdx.x];
}

// ---------------- final head --------------------------------------------------
__global__ void final_mlp_kernel(const float* __restrict__ Wf, const float* __restrict__ bf,
                                 const float* __restrict__ Ws, const float* __restrict__ bs,
                                 float* __restrict__ out, int n, int nblocks) {
    __shared__ float pooled[16];
    __shared__ float hidden[8];
    __shared__ float scores[10];
    int t = threadIdx.x;   // 32 threads
    if (t < 16) {
        float sum = 0.0f;
        for (int b = 0; b < nblocks; b++) sum += g_partial[b * 16 + t];
        pooled[t] = sum / (float)n;
    }
    __syncthreads();
    if (t < 8) {
        float a = bf[t];
        for (int k = 0; k < 16; k++) a = fmaf(pooled[k], Wf[k * 8 + t], a);
        hidden[t] = fmaxf(a, 0.0f);
    }
    __syncthreads();
    if (t < 10) {
        float a = bs[t];
        for (int k = 0; k < 8; k++) a = fmaf(hidden[k], Ws[k * 10 + t], a);
        scores[t] = a;
    }
    __syncthreads();
    if (t == 0) {
        float m = scores[0];
        for (int j = 1; j < 10; j++) m = fmaxf(m, scores[j]);
        float sum = 0.0f;
        for (int j = 0; j < 10; j++) sum += expf(scores[j] - m);
        float lse = m + logf(sum);
        for (int j = 0; j < 10; j++) out[j] = scores[j] - lse;
    }
}

// ---------------- launch ------------------------------------------------------
extern "C" void kernel_launch(void* const* d_in, const int* in_sizes, int n_in,
                              void* d_out, int out_size) {
    const float* features = (const float*)d_in[0];
    const int*   ei       = (const int*)d_in[1];   // int32 (JAX default int width)
    const float* W1 = (const float*)d_in[2];  const float* b1 = (const float*)d_in[3];
    const float* W2 = (const float*)d_in[4];  const float* b2 = (const float*)d_in[5];
    const float* W3 = (const float*)d_in[6];  const float* b3 = (const float*)d_in[7];
    const float* Wf = (const float*)d_in[8];  const float* bf = (const float*)d_in[9];
    const float* Ws = (const float*)d_in[10]; const float* bs = (const float*)d_in[11];

    int N = in_sizes[0] / 256;
    int E = in_sizes[1] / 2;

    int nbE2 = ((E + 1) / 2 + 255) / 256;       // 2 edges/thread kernels
    int nbScan = (N + SCAN_B - 1) / SCAN_B;

    // ---- CSR build + layer-1 GEMM ----
    // gemm1 placed as the 4th kernel launch so the harness ncu capture
    // (which samples the 4th launch) finally profiles it. It only needs
    // dinv (from scan1); csr_fill has no dependency on it.
    void* deg_ptr = nullptr;
    cudaGetSymbolAddress(&deg_ptr, g_deg);
    cudaMemsetAsync(deg_ptr, 0, (size_t)N * sizeof(int));   // graph-capturable
    deg_count_kernel<<<nbE2, 256>>>(ei, E);     // 1st: also captures per-edge rank
    scan1_kernel<<<nbScan, SCAN_B>>>(N);        // 2nd: offsets + dinv
    scan23_kernel<<<nbScan, SCAN_B>>>(N, nbScan); // 3rd
    gemm_scaled_kernel<<<(N + 255) / 256, 128>>>(features, W1, N);  // 4th (profiled)
    csr_fill_kernel<<<nbE2, 256>>>(ei, E);      // 5th: atomic-free

    // ---- fused: agg(64) + GEMM 64->32 (msgA -> msgB) ----
    fused_agg_gemm_kernel<64, 32><<<(N + 31) / 32, 256>>>(b1, W2, N, 0);

    // ---- fused: agg(32) + GEMM 32->16 (msgB -> msgA) ----
    fused_agg_gemm_kernel<32, 16><<<(N + 63) / 64, 256>>>(b2, W3, N, 1);

    // ---- fused: agg(16) + pooling partials (reads msgA) ----
    int nbPool = (N + 127) / 128;
    fused_agg_pool_kernel<<<nbPool, 256>>>(b3, N);

    // ---- head ----
    final_mlp_kernel<<<1, 32>>>(Wf, bf, Ws, bs, (float*)d_out, N, nbPool);
}

// round 16
// speedup vs baseline: 1.0482x; 1.0482x over previous
#include <cuda_runtime.h>
#include <math.h>

// Problem constants (fixed shapes for this problem)
#define NMAX 100000
#define EMAX 3200000
#define SCAN_B 1024

// ---------------- scratch (device globals; no allocation allowed) ------------
__device__ int    g_deg[NMAX];                       // in-degree (int)
__device__ int    g_off[NMAX];                       // CSR exclusive offsets
__device__ int    g_rank[EMAX];                      // edge rank within its dst
__device__ int    g_csr_src[EMAX];                   // src ids, grouped by dst
__device__ int    g_blocksum[128];                   // scan partials
__device__ float  g_dinv[NMAX];                      // rsqrt(deg+1)
// Double-buffered bf16 message arrays (gather input vs GEMM output must be
// distinct buffers: cross-block race otherwise).
__device__ uint4  g_msgA[(size_t)NMAX * 8];          // 8 uint4 = 64 bf16 / node
__device__ uint4  g_msgB[(size_t)NMAX * 8];
__device__ float  g_partial[16384];                  // pooling partials

// ---------------- packed helpers ---------------------------------------------
__device__ __forceinline__ unsigned long long pack_f32x2(float lo, float hi) {
    unsigned long long r;
    asm("mov.b64 %0, {%1, %2};" : "=l"(r) : "f"(lo), "f"(hi));
    return r;
}
__device__ __forceinline__ void fma_f32x2(unsigned long long& d,
                                          unsigned long long a,
                                          unsigned long long b) {
    asm("fma.rn.f32x2 %0, %1, %2, %0;" : "+l"(d) : "l"(a), "l"(b));
}
__device__ __forceinline__ void unpack_f32x2(float& lo, float& hi, unsigned long long v) {
    asm("mov.b64 {%0, %1}, %2;" : "=f"(lo), "=f"(hi) : "l"(v));
}
__device__ __forceinline__ unsigned cvt_bf16x2(float lo, float hi) {
    unsigned r;
    asm("cvt.rn.bf16x2.f32 %0, %1, %2;" : "=r"(r) : "f"(hi), "f"(lo));
    return r;
}
__device__ __forceinline__ void add_bf2(float& a, float& b, unsigned p) {
    a += __uint_as_float(p << 16);
    b += __uint_as_float(p & 0xffff0000u);
}

// ---------------- degree / CSR construction ----------------------------------
// Counts in-degree AND captures each edge's arrival rank within its dst.
__global__ void deg_count_kernel(const int* __restrict__ ei, int E) {
    int e = (blockIdx.x * 256 + threadIdx.x) * 2;
    if (e + 1 < E) {
        int2 d2 = *(const int2*)&ei[E + e];
        g_rank[e]     = atomicAdd(&g_deg[d2.x], 1);
        g_rank[e + 1] = atomicAdd(&g_deg[d2.y], 1);
    } else if (e < E) {
        g_rank[e] = atomicAdd(&g_deg[ei[E + e]], 1);
    }
}

// Shuffle-based block exclusive scan of g_deg -> g_off (+ dinv fold-in).
__global__ void scan1_kernel(int n) {
    __shared__ int warpsum[32];
    int i = blockIdx.x * SCAN_B + threadIdx.x;
    int v = (i < n) ? g_deg[i] : 0;
    if (i < n) g_dinv[i] = rsqrtf((float)v + 1.0f);
    int lane = threadIdx.x & 31;
    int wid = threadIdx.x >> 5;
    int x = v;
#pragma unroll
    for (int off = 1; off < 32; off <<= 1) {
        int y = __shfl_up_sync(0xffffffffu, x, off);
        if (lane >= off) x += y;
    }
    if (lane == 31) warpsum[wid] = x;
    __syncthreads();
    if (wid == 0) {
        int s = warpsum[lane];
#pragma unroll
        for (int off = 1; off < 32; off <<= 1) {
            int y = __shfl_up_sync(0xffffffffu, s, off);
            if (lane >= off) s += y;
        }
        warpsum[lane] = s;
    }
    __syncthreads();
    int base = (wid > 0) ? warpsum[wid - 1] : 0;
    int incl = base + x;
    if (i < n) g_off[i] = incl - v;                  // exclusive within block
    if (threadIdx.x == SCAN_B - 1) g_blocksum[blockIdx.x] = incl;
}

// Merged scan2+scan3: every block redundantly scans the <=128 block totals.
__global__ void scan23_kernel(int n, int nb) {
    __shared__ int ws[4];
    __shared__ int incl128[128];
    int t = threadIdx.x;
    if (t < 128) {
        int lane = t & 31;
        int w = t >> 5;
        int s = (t < nb) ? g_blocksum[t] : 0;
#pragma unroll
        for (int off = 1; off < 32; off <<= 1) {
            int y = __shfl_up_sync(0xffffffffu, s, off);
            if (lane >= off) s += y;
        }
        if (lane == 31) ws[w] = s;
        incl128[t] = s;
    }
    __syncthreads();
    if (t < 128) {
        int w = t >> 5;
        int add = 0;
        for (int u = 0; u < w; u++) add += ws[u];
        incl128[t] += add;
    }
    __syncthreads();
    int add = (blockIdx.x == 0) ? 0 : incl128[blockIdx.x - 1];
    int i = blockIdx.x * SCAN_B + t;
    if (i < n) g_off[i] += add;
}

// Atomic-free CSR fill: pos = off[dst] + rank (captured during counting).
__global__ void csr_fill_kernel(const int* __restrict__ ei, int E) {
    int e = (blockIdx.x * 256 + threadIdx.x) * 2;
    if (e + 1 < E) {
        int2 s2 = *(const int2*)&ei[e];
        int2 d2 = *(const int2*)&ei[E + e];
        int2 r2 = *(const int2*)&g_rank[e];
        g_csr_src[g_off[d2.x] + r2.x] = s2.x;
        g_csr_src[g_off[d2.y] + r2.y] = s2.y;
    } else if (e < E) {
        g_csr_src[g_off[ei[E + e]] + g_rank[e]] = ei[e];
    }
}

// ---------------- layer-1 GEMM: 2 nodes x 32 outputs per thread ---------------
// msgA[node,:] = bf16((X[node,:] @ W) * dinv[node])
// 256 threads, 256 nodes/block. Thread t: half = t&1 (which 32 output cols),
// nodes base+(t>>1) and base+(t>>1)+128. Accumulators: 2 x 16 f32x2 = 64 regs
// (vs 128 in the previous 2x64 scheme -> occupancy 10% -> 25%). Paired threads
// read identical Xs addresses (LDS broadcast). Per-output k-order unchanged.
__global__ void __launch_bounds__(256, 2)
gemm_scaled_kernel(const float* __restrict__ X, const float* __restrict__ W, int n) {
    constexpr int K = 256, NOUT = 64, KC = 32, TS = 33;
    __shared__ float Xs[256 * TS];                  // 33.8 KB
    __shared__ alignas(16) float Wsh[KC * NOUT];    // 8 KB

    const float4* X4 = (const float4*)X;
    int t = threadIdx.x;
    int half = t & 1;                 // output half: cols [half*32, half*32+32)
    int ln = t >> 1;                  // 0..127
    int base = blockIdx.x * 256;
    int n0 = base + ln, n1 = base + ln + 128;
    bool v0 = n0 < n, v1 = n1 < n;

    unsigned long long acc0[16], acc1[16];          // 16 f32x2 per node
#pragma unroll
    for (int j = 0; j < 16; j++) { acc0[j] = 0ull; acc1[j] = 0ull; }

    for (int k0 = 0; k0 < K; k0 += KC) {
        __syncthreads();
        // stage W chunk (2048 floats, 8/thread)
        for (int i = t; i < KC * NOUT; i += 256)
            Wsh[i] = W[k0 * NOUT + i];
        // stage X tile: 256 rows x KC floats = 2048 float4, 8/thread.
        // lanes 0-7 cover one full 128B line -> full-line wavefronts.
        for (int f = t; f < 256 * (KC / 4); f += 256) {
            int row = f >> 3;
            int c4 = f & 7;
            float4 val = make_float4(0.f, 0.f, 0.f, 0.f);
            if (base + row < n)
                val = X4[(size_t)(base + row) * (K / 4) + k0 / 4 + c4];
            float* dst = &Xs[row * TS + c4 * 4];
            dst[0] = val.x; dst[1] = val.y; dst[2] = val.z; dst[3] = val.w;
        }
        __syncthreads();

        for (int kk = 0; kk < KC; kk++) {
            float x0 = Xs[ln * TS + kk];            // pair-broadcast
            float x1 = Xs[(ln + 128) * TS + kk];
            unsigned long long p0 = pack_f32x2(x0, x0);
            unsigned long long p1 = pack_f32x2(x1, x1);
            const ulonglong2* wrow2 =
                (const ulonglong2*)&Wsh[kk * NOUT + half * 32];
#pragma unroll
            for (int j = 0; j < 8; j++) {
                ulonglong2 w = wrow2[j];            // 4 floats = 2 f32x2
                fma_f32x2(acc0[2 * j + 0], p0, w.x);
                fma_f32x2(acc0[2 * j + 1], p0, w.y);
                fma_f32x2(acc1[2 * j + 0], p1, w.x);
                fma_f32x2(acc1[2 * j + 1], p1, w.y);
            }
        }
    }

    // epilogue: 32 outputs per node -> 4 uint4 (8 bf16 each) at half*4 offset
    if (v0) {
        float dv = g_dinv[n0];
#pragma unroll
        for (int q = 0; q < 4; q++) {
            unsigned r[4];
#pragma unroll
            for (int u = 0; u < 4; u++) {
                float lo, hi;
                unpack_f32x2(lo, hi, acc0[4 * q + u]);
                r[u] = cvt_bf16x2(lo * dv, hi * dv);
            }
            g_msgA[(size_t)n0 * 8 + half * 4 + q] = make_uint4(r[0], r[1], r[2], r[3]);
        }
    }
    if (v1) {
        float dv = g_dinv[n1];
#pragma unroll
        for (int q = 0; q < 4; q++) {
            unsigned r[4];
#pragma unroll
            for (int u = 0; u < 4; u++) {
                float lo, hi;
                unpack_f32x2(lo, hi, acc1[4 * q + u]);
                r[u] = cvt_bf16x2(lo * dv, hi * dv);
            }
            g_msgA[(size_t)n1 * 8 + half * 4 + q] = make_uint4(r[0], r[1], r[2], r[3]);
        }
    }
}

// ---------------- fused aggregate + next-layer GEMM (warp-autonomous) ---------
// dir=0: in=msgA out=msgB ; dir=1: in=msgB out=msgA
template <int NIN, int NOUT>
__global__ void fused_agg_gemm_kernel(const float* __restrict__ bias,
                                      const float* __restrict__ W,
                                      int n, int dir) {
    constexpr int CH = NIN / 8;                  // lanes per node (agg phase)
    constexpr int NPB = 256 / CH;                // nodes per block
    constexpr int HS = NIN + 4;                  // padded h row (floats)
    __shared__ alignas(16) float Wsh[NIN * NOUT];
    __shared__ alignas(16) float Hsh[NPB * HS];

    const uint4* __restrict__ msg_in  = dir ? g_msgB : g_msgA;
    uint2* __restrict__       msg_out = dir ? (uint2*)g_msgA : (uint2*)g_msgB;

    int lnode = threadIdx.x / CH;
    int c = threadIdx.x % CH;
    int node = blockIdx.x * NPB + lnode;
    bool valid = node < n;

    for (int i = threadIdx.x; i < NIN * NOUT; i += 256) Wsh[i] = W[i];
    __syncthreads();   // Wsh ready BEFORE divergent gather; no barrier after

    float acc[8];
#pragma unroll
    for (int u = 0; u < 8; u++) acc[u] = 0.0f;

    if (valid) {
        int start = g_off[node];
        int end = start + g_deg[node];
        {
            uint4 sv = msg_in[(size_t)node * CH + c];   // self-loop
            add_bf2(acc[0], acc[1], sv.x);
            add_bf2(acc[2], acc[3], sv.y);
            add_bf2(acc[4], acc[5], sv.z);
            add_bf2(acc[6], acc[7], sv.w);
        }
        int e = start;
        for (; e + 8 <= end; e += 8) {
            int sidx[8];
#pragma unroll
            for (int u = 0; u < 8; u++) sidx[u] = g_csr_src[e + u];
            uint4 v[8];
#pragma unroll
            for (int u = 0; u < 8; u++) v[u] = msg_in[(size_t)sidx[u] * CH + c];
#pragma unroll
            for (int u = 0; u < 8; u++) {
                add_bf2(acc[0], acc[1], v[u].x);
                add_bf2(acc[2], acc[3], v[u].y);
                add_bf2(acc[4], acc[5], v[u].z);
                add_bf2(acc[6], acc[7], v[u].w);
            }
        }
        for (; e < end; e++) {
            uint4 v = msg_in[(size_t)g_csr_src[e] * CH + c];
            add_bf2(acc[0], acc[1], v.x);
            add_bf2(acc[2], acc[3], v.y);
            add_bf2(acc[4], acc[5], v.z);
            add_bf2(acc[6], acc[7], v.w);
        }
        float dv = g_dinv[node];
        const float4* b4 = (const float4*)bias;
        float4 bl = b4[c * 2 + 0];
        float4 bh = b4[c * 2 + 1];
        acc[0] = fmaxf(fmaf(dv, acc[0], bl.x), 0.0f);
        acc[1] = fmaxf(fmaf(dv, acc[1], bl.y), 0.0f);
        acc[2] = fmaxf(fmaf(dv, acc[2], bl.z), 0.0f);
        acc[3] = fmaxf(fmaf(dv, acc[3], bl.w), 0.0f);
        acc[4] = fmaxf(fmaf(dv, acc[4], bh.x), 0.0f);
        acc[5] = fmaxf(fmaf(dv, acc[5], bh.y), 0.0f);
        acc[6] = fmaxf(fmaf(dv, acc[6], bh.z), 0.0f);
        acc[7] = fmaxf(fmaf(dv, acc[7], bh.w), 0.0f);
    }
    float* hrow = &Hsh[lnode * HS];
    *(float4*)&hrow[c * 8 + 0] = make_float4(acc[0], acc[1], acc[2], acc[3]);
    *(float4*)&hrow[c * 8 + 4] = make_float4(acc[4], acc[5], acc[6], acc[7]);
    __syncwarp();      // h rows for this warp's nodes are warp-local

    if (valid) {
        unsigned long long a0 = 0ull, a1 = 0ull;         // outputs c*4..c*4+3
#pragma unroll
        for (int k = 0; k < NIN; k += 4) {
            float4 x4 = *(const float4*)&hrow[k];
            float xs[4] = {x4.x, x4.y, x4.z, x4.w};
#pragma unroll
            for (int t = 0; t < 4; t++) {
                unsigned long long x2 = pack_f32x2(xs[t], xs[t]);
                ulonglong2 w = *(const ulonglong2*)&Wsh[(k + t) * NOUT + c * 4];
                fma_f32x2(a0, x2, w.x);
                fma_f32x2(a1, x2, w.y);
            }
        }
        float dv = g_dinv[node];
        float o0, o1, o2, o3;
        unpack_f32x2(o0, o1, a0);
        unpack_f32x2(o2, o3, a1);
        uint2 pk;
        pk.x = cvt_bf16x2(o0 * dv, o1 * dv);
        pk.y = cvt_bf16x2(o2 * dv, o3 * dv);
        msg_out[(size_t)node * (NOUT / 4) + c] = pk;
    }
}

// ---------------- fused aggregate (16 feats) + block pooling ------------------
__global__ void fused_agg_pool_kernel(const float* __restrict__ bias, int n) {
    constexpr int CH = 2, NPB = 128, HS = 16;
    __shared__ float Hsh[NPB * HS];
    __shared__ float s[256];

    int lnode = threadIdx.x / CH;
    int c = threadIdx.x % CH;
    int node = blockIdx.x * NPB + lnode;
    bool valid = node < n;

    float acc[8];
#pragma unroll
    for (int u = 0; u < 8; u++) acc[u] = 0.0f;

    if (valid) {
        int start = g_off[node];
        int end = start + g_deg[node];
        {
            uint4 sv = g_msgA[(size_t)node * CH + c];
            add_bf2(acc[0], acc[1], sv.x);
            add_bf2(acc[2], acc[3], sv.y);
            add_bf2(acc[4], acc[5], sv.z);
            add_bf2(acc[6], acc[7], sv.w);
        }
        int e = start;
        for (; e + 8 <= end; e += 8) {
            int sidx[8];
#pragma unroll
            for (int u = 0; u < 8; u++) sidx[u] = g_csr_src[e + u];
            uint4 v[8];
#pragma unroll
            for (int u = 0; u < 8; u++) v[u] = g_msgA[(size_t)sidx[u] * CH + c];
#pragma unroll
            for (int u = 0; u < 8; u++) {
                add_bf2(acc[0], acc[1], v[u].x);
                add_bf2(acc[2], acc[3], v[u].y);
                add_bf2(acc[4], acc[5], v[u].z);
                add_bf2(acc[6], acc[7], v[u].w);
            }
        }
        for (; e < end; e++) {
            uint4 v = g_msgA[(size_t)g_csr_src[e] * CH + c];
            add_bf2(acc[0], acc[1], v.x);
            add_bf2(acc[2], acc[3], v.y);
            add_bf2(acc[4], acc[5], v.z);
            add_bf2(acc[6], acc[7], v.w);
        }
        float dv = g_dinv[node];
        const float4* b4 = (const float4*)bias;
        float4 bl = b4[c * 2 + 0];
        float4 bh = b4[c * 2 + 1];
        acc[0] = fmaxf(fmaf(dv, acc[0], bl.x), 0.0f);
        acc[1] = fmaxf(fmaf(dv, acc[1], bl.y), 0.0f);
        acc[2] = fmaxf(fmaf(dv, acc[2], bl.z), 0.0f);
        acc[3] = fmaxf(fmaf(dv, acc[3], bl.w), 0.0f);
        acc[4] = fmaxf(fmaf(dv, acc[4], bh.x), 0.0f);
        acc[5] = fmaxf(fmaf(dv, acc[5], bh.y), 0.0f);
        acc[6] = fmaxf(fmaf(dv, acc[6], bh.z), 0.0f);
        acc[7] = fmaxf(fmaf(dv, acc[7], bh.w), 0.0f);
    }
    float* hrow = &Hsh[lnode * HS];
    *(float4*)&hrow[c * 8 + 0] = make_float4(acc[0], acc[1], acc[2], acc[3]);
    *(float4*)&hrow[c * 8 + 4] = make_float4(acc[4], acc[5], acc[6], acc[7]);
    __syncthreads();

    int f = threadIdx.x & 15;
    int grp = threadIdx.x >> 4;
    float sum = 0.0f;
#pragma unroll
    for (int u = 0; u < 8; u++)
        sum += Hsh[(grp + u * 16) * HS + f];
    s[threadIdx.x] = sum;
    __syncthreads();
    for (int off = 128; off >= 16; off >>= 1) {
        if (threadIdx.x < off) s[threadIdx.x] += s[threadIdx.x + off];
        __syncthreads();
    }
    if (threadIdx.x < 16) g_partial[blockIdx.x * 16 + threadIdx.x] = s[threadIdx.x];
}

// ---------------- final head --------------------------------------------------
__global__ void final_mlp_kernel(const float* __restrict__ Wf, const float* __restrict__ bf,
                                 const float* __restrict__ Ws, const float* __restrict__ bs,
                                 float* __restrict__ out, int n, int nblocks) {
    __shared__ float pooled[16];
    __shared__ float hidden[8];
    __shared__ float scores[10];
    int t = threadIdx.x;   // 32 threads
    if (t < 16) {
        float sum = 0.0f;
        for (int b = 0; b < nblocks; b++) sum += g_partial[b * 16 + t];
        pooled[t] = sum / (float)n;
    }
    __syncthreads();
    if (t < 8) {
        float a = bf[t];
        for (int k = 0; k < 16; k++) a = fmaf(pooled[k], Wf[k * 8 + t], a);
        hidden[t] = fmaxf(a, 0.0f);
    }
    __syncthreads();
    if (t < 10) {
        float a = bs[t];
        for (int k = 0; k < 8; k++) a = fmaf(hidden[k], Ws[k * 10 + t], a);
        scores[t] = a;
    }
    __syncthreads();
    if (t == 0) {
        float m = scores[0];
        for (int j = 1; j < 10; j++) m = fmaxf(m, scores[j]);
        float sum = 0.0f;
        for (int j = 0; j < 10; j++) sum += expf(scores[j] - m);
        float lse = m + logf(sum);
        for (int j = 0; j < 10; j++) out[j] = scores[j] - lse;
    }
}

// ---------------- launch ------------------------------------------------------
extern "C" void kernel_launch(void* const* d_in, const int* in_sizes, int n_in,
                              void* d_out, int out_size) {
    const float* features = (const float*)d_in[0];
    const int*   ei       = (const int*)d_in[1];   // int32 (JAX default int width)
    const float* W1 = (const float*)d_in[2];  const float* b1 = (const float*)d_in[3];
    const float* W2 = (const float*)d_in[4];  const float* b2 = (const float*)d_in[5];
    const float* W3 = (const float*)d_in[6];  const float* b3 = (const float*)d_in[7];
    const float* Wf = (const float*)d_in[8];  const float* bf = (const float*)d_in[9];
    const float* Ws = (const float*)d_in[10]; const float* bs = (const float*)d_in[11];

    int N = in_sizes[0] / 256;
    int E = in_sizes[1] / 2;

    int nbE2 = ((E + 1) / 2 + 255) / 256;       // 2 edges/thread kernels
    int nbScan = (N + SCAN_B - 1) / SCAN_B;

    // ---- CSR build + layer-1 GEMM (gemm kept as 4th launch for profiling) ----
    void* deg_ptr = nullptr;
    cudaGetSymbolAddress(&deg_ptr, g_deg);
    cudaMemsetAsync(deg_ptr, 0, (size_t)N * sizeof(int));   // graph-capturable
    deg_count_kernel<<<nbE2, 256>>>(ei, E);     // 1st: also captures per-edge rank
    scan1_kernel<<<nbScan, SCAN_B>>>(N);        // 2nd: offsets + dinv
    scan23_kernel<<<nbScan, SCAN_B>>>(N, nbScan); // 3rd
    gemm_scaled_kernel<<<(N + 255) / 256, 256>>>(features, W1, N);  // 4th (profiled)
    csr_fill_kernel<<<nbE2, 256>>>(ei, E);      // 5th: atomic-free

    // ---- fused: agg(64) + GEMM 64->32 (msgA -> msgB) ----
    fused_agg_gemm_kernel<64, 32><<<(N + 31) / 32, 256>>>(b1, W2, N, 0);

    // ---- fused: agg(32) + GEMM 32->16 (msgB -> msgA) ----
    fused_agg_gemm_kernel<32, 16><<<(N + 63) / 64, 256>>>(b2, W3, N, 1);

    // ---- fused: agg(16) + pooling partials (reads msgA) ----
    int nbPool = (N + 127) / 128;
    fused_agg_pool_kernel<<<nbPool, 256>>>(b3, N);

    // ---- head ----
    final_mlp_kernel<<<1, 32>>>(Wf, bf, Ws, bs, (float*)d_out, N, nbPool);
}

// round 17
// speedup vs baseline: 1.1346x; 1.0824x over previous
#include <cuda_runtime.h>
#include <math.h>

// Problem constants (fixed shapes for this problem)
#define NMAX 100000
#define EMAX 3200000
#define SCAN_B 1024

// ---------------- scratch (device globals; no allocation allowed) ------------
__device__ int    g_deg[NMAX];                       // in-degree (int)
__device__ int    g_off[NMAX];                       // CSR exclusive offsets
__device__ int    g_rank[EMAX];                      // edge rank within its dst
__device__ int    g_csr_src[EMAX];                   // src ids, grouped by dst
__device__ int    g_blocksum[128];                   // scan partials
__device__ float  g_dinv[NMAX];                      // rsqrt(deg+1)
// Double-buffered bf16 message arrays (gather input vs GEMM output must be
// distinct buffers: cross-block race otherwise).
__device__ uint4  g_msgA[(size_t)NMAX * 8];          // 8 uint4 = 64 bf16 / node
__device__ uint4  g_msgB[(size_t)NMAX * 8];
__device__ float  g_partial[16384];                  // pooling partials

// ---------------- packed helpers ---------------------------------------------
__device__ __forceinline__ unsigned long long pack_f32x2(float lo, float hi) {
    unsigned long long r;
    asm("mov.b64 %0, {%1, %2};" : "=l"(r) : "f"(lo), "f"(hi));
    return r;
}
__device__ __forceinline__ void fma_f32x2(unsigned long long& d,
                                          unsigned long long a,
                                          unsigned long long b) {
    asm("fma.rn.f32x2 %0, %1, %2, %0;" : "+l"(d) : "l"(a), "l"(b));
}
__device__ __forceinline__ void unpack_f32x2(float& lo, float& hi, unsigned long long v) {
    asm("mov.b64 {%0, %1}, %2;" : "=f"(lo), "=f"(hi) : "l"(v));
}
__device__ __forceinline__ unsigned cvt_bf16x2(float lo, float hi) {
    unsigned r;
    asm("cvt.rn.bf16x2.f32 %0, %1, %2;" : "=r"(r) : "f"(hi), "f"(lo));
    return r;
}
__device__ __forceinline__ void add_bf2(float& a, float& b, unsigned p) {
    a += __uint_as_float(p << 16);
    b += __uint_as_float(p & 0xffff0000u);
}

// ---------------- degree / CSR construction ----------------------------------
// Counts in-degree AND captures each edge's arrival rank within its dst.
__global__ void deg_count_kernel(const int* __restrict__ ei, int E) {
    int e = (blockIdx.x * 256 + threadIdx.x) * 2;
    if (e + 1 < E) {
        int2 d2 = *(const int2*)&ei[E + e];
        g_rank[e]     = atomicAdd(&g_deg[d2.x], 1);
        g_rank[e + 1] = atomicAdd(&g_deg[d2.y], 1);
    } else if (e < E) {
        g_rank[e] = atomicAdd(&g_deg[ei[E + e]], 1);
    }
}

// Shuffle-based block exclusive scan of g_deg -> g_off (+ dinv fold-in).
__global__ void scan1_kernel(int n) {
    __shared__ int warpsum[32];
    int i = blockIdx.x * SCAN_B + threadIdx.x;
    int v = (i < n) ? g_deg[i] : 0;
    if (i < n) g_dinv[i] = rsqrtf((float)v + 1.0f);
    int lane = threadIdx.x & 31;
    int wid = threadIdx.x >> 5;
    int x = v;
#pragma unroll
    for (int off = 1; off < 32; off <<= 1) {
        int y = __shfl_up_sync(0xffffffffu, x, off);
        if (lane >= off) x += y;
    }
    if (lane == 31) warpsum[wid] = x;
    __syncthreads();
    if (wid == 0) {
        int s = warpsum[lane];
#pragma unroll
        for (int off = 1; off < 32; off <<= 1) {
            int y = __shfl_up_sync(0xffffffffu, s, off);
            if (lane >= off) s += y;
        }
        warpsum[lane] = s;
    }
    __syncthreads();
    int base = (wid > 0) ? warpsum[wid - 1] : 0;
    int incl = base + x;
    if (i < n) g_off[i] = incl - v;                  // exclusive within block
    if (threadIdx.x == SCAN_B - 1) g_blocksum[blockIdx.x] = incl;
}

// Merged scan2+scan3: every block redundantly scans the <=128 block totals.
__global__ void scan23_kernel(int n, int nb) {
    __shared__ int ws[4];
    __shared__ int incl128[128];
    int t = threadIdx.x;
    if (t < 128) {
        int lane = t & 31;
        int w = t >> 5;
        int s = (t < nb) ? g_blocksum[t] : 0;
#pragma unroll
        for (int off = 1; off < 32; off <<= 1) {
            int y = __shfl_up_sync(0xffffffffu, s, off);
            if (lane >= off) s += y;
        }
        if (lane == 31) ws[w] = s;
        incl128[t] = s;
    }
    __syncthreads();
    if (t < 128) {
        int w = t >> 5;
        int add = 0;
        for (int u = 0; u < w; u++) add += ws[u];
        incl128[t] += add;
    }
    __syncthreads();
    int add = (blockIdx.x == 0) ? 0 : incl128[blockIdx.x - 1];
    int i = blockIdx.x * SCAN_B + t;
    if (i < n) g_off[i] += add;
}

// Atomic-free CSR fill: pos = off[dst] + rank (captured during counting).
__global__ void csr_fill_kernel(const int* __restrict__ ei, int E) {
    int e = (blockIdx.x * 256 + threadIdx.x) * 2;
    if (e + 1 < E) {
        int2 s2 = *(const int2*)&ei[e];
        int2 d2 = *(const int2*)&ei[E + e];
        int2 r2 = *(const int2*)&g_rank[e];
        g_csr_src[g_off[d2.x] + r2.x] = s2.x;
        g_csr_src[g_off[d2.y] + r2.y] = s2.y;
    } else if (e < E) {
        g_csr_src[g_off[ei[E + e]] + g_rank[e]] = ei[e];
    }
}

// ---------------- layer-1 GEMM: warp-uniform W reads --------------------------
// msgA[node,:] = bf16((X[node,:] @ W) * dinv[node])
// 256 threads = 8 warps, 256 nodes/block. Output half mapped to WARP index:
// warps 0-3 -> cols [0,32), warps 4-7 -> cols [32,64); lnode = (w&3)*32+lane.
// At fixed (kk,j) every lane in a warp reads the SAME Wsh address -> LDS.128
// broadcast = 1 wavefront (the previous pair-interleaved map cost 4). x reads
// hit banks (lane+kk)%32 -> conflict-free. Per-output k-order unchanged.
__global__ void __launch_bounds__(256, 2)
gemm_scaled_kernel(const float* __restrict__ X, const float* __restrict__ W, int n) {
    constexpr int K = 256, NOUT = 64, KC = 32, TS = 33;
    __shared__ float Xs[256 * TS];                  // 33.8 KB
    __shared__ alignas(16) float Wsh[KC * NOUT];    // 8 KB

    const float4* X4 = (const float4*)X;
    int t = threadIdx.x;
    int lane = t & 31;
    int w = t >> 5;                   // 0..7
    int half = w >> 2;                // warp-uniform output half
    int lnode = (w & 3) * 32 + lane;  // 0..127
    int base = blockIdx.x * 256;
    int n0 = base + lnode, n1 = base + lnode + 128;
    bool v0 = n0 < n, v1 = n1 < n;

    unsigned long long acc0[16], acc1[16];          // 16 f32x2 per node
#pragma unroll
    for (int j = 0; j < 16; j++) { acc0[j] = 0ull; acc1[j] = 0ull; }

    for (int k0 = 0; k0 < K; k0 += KC) {
        __syncthreads();
        // stage W chunk (2048 floats, 8/thread)
        for (int i = t; i < KC * NOUT; i += 256)
            Wsh[i] = W[k0 * NOUT + i];
        // stage X tile: 256 rows x KC floats = 2048 float4, 8/thread.
        for (int f = t; f < 256 * (KC / 4); f += 256) {
            int row = f >> 3;
            int c4 = f & 7;
            float4 val = make_float4(0.f, 0.f, 0.f, 0.f);
            if (base + row < n)
                val = X4[(size_t)(base + row) * (K / 4) + k0 / 4 + c4];
            float* dst = &Xs[row * TS + c4 * 4];
            dst[0] = val.x; dst[1] = val.y; dst[2] = val.z; dst[3] = val.w;
        }
        __syncthreads();

        for (int kk = 0; kk < KC; kk++) {
            float x0 = Xs[lnode * TS + kk];           // conflict-free
            float x1 = Xs[(lnode + 128) * TS + kk];
            unsigned long long p0 = pack_f32x2(x0, x0);
            unsigned long long p1 = pack_f32x2(x1, x1);
            const ulonglong2* wrow2 =
                (const ulonglong2*)&Wsh[kk * NOUT + half * 32];  // warp-uniform
#pragma unroll
            for (int j = 0; j < 8; j++) {
                ulonglong2 wv = wrow2[j];             // broadcast LDS.128
                fma_f32x2(acc0[2 * j + 0], p0, wv.x);
                fma_f32x2(acc0[2 * j + 1], p0, wv.y);
                fma_f32x2(acc1[2 * j + 0], p1, wv.x);
                fma_f32x2(acc1[2 * j + 1], p1, wv.y);
            }
        }
    }

    // epilogue: 32 outputs per node -> 4 uint4 (8 bf16 each) at half*4 offset
    if (v0) {
        float dv = g_dinv[n0];
#pragma unroll
        for (int q = 0; q < 4; q++) {
            unsigned r[4];
#pragma unroll
            for (int u = 0; u < 4; u++) {
                float lo, hi;
                unpack_f32x2(lo, hi, acc0[4 * q + u]);
                r[u] = cvt_bf16x2(lo * dv, hi * dv);
            }
            g_msgA[(size_t)n0 * 8 + half * 4 + q] = make_uint4(r[0], r[1], r[2], r[3]);
        }
    }
    if (v1) {
        float dv = g_dinv[n1];
#pragma unroll
        for (int q = 0; q < 4; q++) {
            unsigned r[4];
#pragma unroll
            for (int u = 0; u < 4; u++) {
                float lo, hi;
                unpack_f32x2(lo, hi, acc1[4 * q + u]);
                r[u] = cvt_bf16x2(lo * dv, hi * dv);
            }
            g_msgA[(size_t)n1 * 8 + half * 4 + q] = make_uint4(r[0], r[1], r[2], r[3]);
        }
    }
}

// ---------------- fused aggregate + next-layer GEMM (warp-autonomous) ---------
// dir=0: in=msgA out=msgB ; dir=1: in=msgB out=msgA
template <int NIN, int NOUT>
__global__ void fused_agg_gemm_kernel(const float* __restrict__ bias,
                                      const float* __restrict__ W,
                                      int n, int dir) {
    constexpr int CH = NIN / 8;                  // lanes per node (agg phase)
    constexpr int NPB = 256 / CH;                // nodes per block
    constexpr int HS = NIN + 4;                  // padded h row (floats)
    __shared__ alignas(16) float Wsh[NIN * NOUT];
    __shared__ alignas(16) float Hsh[NPB * HS];

    const uint4* __restrict__ msg_in  = dir ? g_msgB : g_msgA;
    uint2* __restrict__       msg_out = dir ? (uint2*)g_msgA : (uint2*)g_msgB;

    int lnode = threadIdx.x / CH;
    int c = threadIdx.x % CH;
    int node = blockIdx.x * NPB + lnode;
    bool valid = node < n;

    for (int i = threadIdx.x; i < NIN * NOUT; i += 256) Wsh[i] = W[i];
    __syncthreads();   // Wsh ready BEFORE divergent gather; no barrier after

    float acc[8];
#pragma unroll
    for (int u = 0; u < 8; u++) acc[u] = 0.0f;

    if (valid) {
        int start = g_off[node];
        int end = start + g_deg[node];
        {
            uint4 sv = msg_in[(size_t)node * CH + c];   // self-loop
            add_bf2(acc[0], acc[1], sv.x);
            add_bf2(acc[2], acc[3], sv.y);
            add_bf2(acc[4], acc[5], sv.z);
            add_bf2(acc[6], acc[7], sv.w);
        }
        int e = start;
        for (; e + 8 <= end; e += 8) {
            int sidx[8];
#pragma unroll
            for (int u = 0; u < 8; u++) sidx[u] = g_csr_src[e + u];
            uint4 v[8];
#pragma unroll
            for (int u = 0; u < 8; u++) v[u] = msg_in[(size_t)sidx[u] * CH + c];
#pragma unroll
            for (int u = 0; u < 8; u++) {
                add_bf2(acc[0], acc[1], v[u].x);
                add_bf2(acc[2], acc[3], v[u].y);
                add_bf2(acc[4], acc[5], v[u].z);
                add_bf2(acc[6], acc[7], v[u].w);
            }
        }
        for (; e < end; e++) {
            uint4 v = msg_in[(size_t)g_csr_src[e] * CH + c];
            add_bf2(acc[0], acc[1], v.x);
            add_bf2(acc[2], acc[3], v.y);
            add_bf2(acc[4], acc[5], v.z);
            add_bf2(acc[6], acc[7], v.w);
        }
        float dv = g_dinv[node];
        const float4* b4 = (const float4*)bias;
        float4 bl = b4[c * 2 + 0];
        float4 bh = b4[c * 2 + 1];
        acc[0] = fmaxf(fmaf(dv, acc[0], bl.x), 0.0f);
        acc[1] = fmaxf(fmaf(dv, acc[1], bl.y), 0.0f);
        acc[2] = fmaxf(fmaf(dv, acc[2], bl.z), 0.0f);
        acc[3] = fmaxf(fmaf(dv, acc[3], bl.w), 0.0f);
        acc[4] = fmaxf(fmaf(dv, acc[4], bh.x), 0.0f);
        acc[5] = fmaxf(fmaf(dv, acc[5], bh.y), 0.0f);
        acc[6] = fmaxf(fmaf(dv, acc[6], bh.z), 0.0f);
        acc[7] = fmaxf(fmaf(dv, acc[7], bh.w), 0.0f);
    }
    float* hrow = &Hsh[lnode * HS];
    *(float4*)&hrow[c * 8 + 0] = make_float4(acc[0], acc[1], acc[2], acc[3]);
    *(float4*)&hrow[c * 8 + 4] = make_float4(acc[4], acc[5], acc[6], acc[7]);
    __syncwarp();      // h rows for this warp's nodes are warp-local

    if (valid) {
        unsigned long long a0 = 0ull, a1 = 0ull;         // outputs c*4..c*4+3
#pragma unroll
        for (int k = 0; k < NIN; k += 4) {
            float4 x4 = *(const float4*)&hrow[k];
            float xs[4] = {x4.x, x4.y, x4.z, x4.w};
#pragma unroll
            for (int t = 0; t < 4; t++) {
                unsigned long long x2 = pack_f32x2(xs[t], xs[t]);
                ulonglong2 w = *(const ulonglong2*)&Wsh[(k + t) * NOUT + c * 4];
                fma_f32x2(a0, x2, w.x);
                fma_f32x2(a1, x2, w.y);
            }
        }
        float dv = g_dinv[node];
        float o0, o1, o2, o3;
        unpack_f32x2(o0, o1, a0);
        unpack_f32x2(o2, o3, a1);
        uint2 pk;
        pk.x = cvt_bf16x2(o0 * dv, o1 * dv);
        pk.y = cvt_bf16x2(o2 * dv, o3 * dv);
        msg_out[(size_t)node * (NOUT / 4) + c] = pk;
    }
}

// ---------------- fused aggregate (16 feats) + block pooling ------------------
__global__ void fused_agg_pool_kernel(const float* __restrict__ bias, int n) {
    constexpr int CH = 2, NPB = 128, HS = 16;
    __shared__ float Hsh[NPB * HS];
    __shared__ float s[256];

    int lnode = threadIdx.x / CH;
    int c = threadIdx.x % CH;
    int node = blockIdx.x * NPB + lnode;
    bool valid = node < n;

    float acc[8];
#pragma unroll
    for (int u = 0; u < 8; u++) acc[u] = 0.0f;

    if (valid) {
        int start = g_off[node];
        int end = start + g_deg[node];
        {
            uint4 sv = g_msgA[(size_t)node * CH + c];
            add_bf2(acc[0], acc[1], sv.x);
            add_bf2(acc[2], acc[3], sv.y);
            add_bf2(acc[4], acc[5], sv.z);
            add_bf2(acc[6], acc[7], sv.w);
        }
        int e = start;
        for (; e + 8 <= end; e += 8) {
            int sidx[8];
#pragma unroll
            for (int u = 0; u < 8; u++) sidx[u] = g_csr_src[e + u];
            uint4 v[8];
#pragma unroll
            for (int u = 0; u < 8; u++) v[u] = g_msgA[(size_t)sidx[u] * CH + c];
#pragma unroll
            for (int u = 0; u < 8; u++) {
                add_bf2(acc[0], acc[1], v[u].x);
                add_bf2(acc[2], acc[3], v[u].y);
                add_bf2(acc[4], acc[5], v[u].z);
                add_bf2(acc[6], acc[7], v[u].w);
            }
        }
        for (; e < end; e++) {
            uint4 v = g_msgA[(size_t)g_csr_src[e] * CH + c];
            add_bf2(acc[0], acc[1], v.x);
            add_bf2(acc[2], acc[3], v.y);
            add_bf2(acc[4], acc[5], v.z);
            add_bf2(acc[6], acc[7], v.w);
        }
        float dv = g_dinv[node];
        const float4* b4 = (const float4*)bias;
        float4 bl = b4[c * 2 + 0];
        float4 bh = b4[c * 2 + 1];
        acc[0] = fmaxf(fmaf(dv, acc[0], bl.x), 0.0f);
        acc[1] = fmaxf(fmaf(dv, acc[1], bl.y), 0.0f);
        acc[2] = fmaxf(fmaf(dv, acc[2], bl.z), 0.0f);
        acc[3] = fmaxf(fmaf(dv, acc[3], bl.w), 0.0f);
        acc[4] = fmaxf(fmaf(dv, acc[4], bh.x), 0.0f);
        acc[5] = fmaxf(fmaf(dv, acc[5], bh.y), 0.0f);
        acc[6] = fmaxf(fmaf(dv, acc[6], bh.z), 0.0f);
        acc[7] = fmaxf(fmaf(dv, acc[7], bh.w), 0.0f);
    }
    float* hrow = &Hsh[lnode * HS];
    *(float4*)&hrow[c * 8 + 0] = make_float4(acc[0], acc[1], acc[2], acc[3]);
    *(float4*)&hrow[c * 8 + 4] = make_float4(acc[4], acc[5], acc[6], acc[7]);
    __syncthreads();

    int f = threadIdx.x & 15;
    int grp = threadIdx.x >> 4;
    float sum = 0.0f;
#pragma unroll
    for (int u = 0; u < 8; u++)
        sum += Hsh[(grp + u * 16) * HS + f];
    s[threadIdx.x] = sum;
    __syncthreads();
    for (int off = 128; off >= 16; off >>= 1) {
        if (threadIdx.x < off) s[threadIdx.x] += s[threadIdx.x + off];
        __syncthreads();
    }
    if (threadIdx.x < 16) g_partial[blockIdx.x * 16 + threadIdx.x] = s[threadIdx.x];
}

// ---------------- final head --------------------------------------------------
__global__ void final_mlp_kernel(const float* __restrict__ Wf, const float* __restrict__ bf,
                                 const float* __restrict__ Ws, const float* __restrict__ bs,
                                 float* __restrict__ out, int n, int nblocks) {
    __shared__ float pooled[16];
    __shared__ float hidden[8];
    __shared__ float scores[10];
    int t = threadIdx.x;   // 32 threads
    if (t < 16) {
        float sum = 0.0f;
        for (int b = 0; b < nblocks; b++) sum += g_partial[b * 16 + t];
        pooled[t] = sum / (float)n;
    }
    __syncthreads();
    if (t < 8) {
        float a = bf[t];
        for (int k = 0; k < 16; k++) a = fmaf(pooled[k], Wf[k * 8 + t], a);
        hidden[t] = fmaxf(a, 0.0f);
    }
    __syncthreads();
    if (t < 10) {
        float a = bs[t];
        for (int k = 0; k < 8; k++) a = fmaf(hidden[k], Ws[k * 10 + t], a);
        scores[t] = a;
    }
    __syncthreads();
    if (t == 0) {
        float m = scores[0];
        for (int j = 1; j < 10; j++) m = fmaxf(m, scores[j]);
        float sum = 0.0f;
        for (int j = 0; j < 10; j++) sum += expf(scores[j] - m);
        float lse = m + logf(sum);
        for (int j = 0; j < 10; j++) out[j] = scores[j] - lse;
    }
}

// ---------------- launch ------------------------------------------------------
extern "C" void kernel_launch(void* const* d_in, const int* in_sizes, int n_in,
                              void* d_out, int out_size) {
    const float* features = (const float*)d_in[0];
    const int*   ei       = (const int*)d_in[1];   // int32 (JAX default int width)
    const float* W1 = (const float*)d_in[2];  const float* b1 = (const float*)d_in[3];
    const float* W2 = (const float*)d_in[4];  const float* b2 = (const float*)d_in[5];
    const float* W3 = (const float*)d_in[6];  const float* b3 = (const float*)d_in[7];
    const float* Wf = (const float*)d_in[8];  const float* bf = (const float*)d_in[9];
    const float* Ws = (const float*)d_in[10]; const float* bs = (const float*)d_in[11];

    int N = in_sizes[0] / 256;
    int E = in_sizes[1] / 2;

    int nbE2 = ((E + 1) / 2 + 255) / 256;       // 2 edges/thread kernels
    int nbScan = (N + SCAN_B - 1) / SCAN_B;

    // ---- CSR build + layer-1 GEMM (gemm kept as 4th launch for profiling) ----
    void* deg_ptr = nullptr;
    cudaGetSymbolAddress(&deg_ptr, g_deg);
    cudaMemsetAsync(deg_ptr, 0, (size_t)N * sizeof(int));   // graph-capturable
    deg_count_kernel<<<nbE2, 256>>>(ei, E);     // 1st: also captures per-edge rank
    scan1_kernel<<<nbScan, SCAN_B>>>(N);        // 2nd: offsets + dinv
    scan23_kernel<<<nbScan, SCAN_B>>>(N, nbScan); // 3rd
    gemm_scaled_kernel<<<(N + 255) / 256, 256>>>(features, W1, N);  // 4th (profiled)
    csr_fill_kernel<<<nbE2, 256>>>(ei, E);      // 5th: atomic-free

    // ---- fused: agg(64) + GEMM 64->32 (msgA -> msgB) ----
    fused_agg_gemm_kernel<64, 32><<<(N + 31) / 32, 256>>>(b1, W2, N, 0);

    // ---- fused: agg(32) + GEMM 32->16 (msgB -> msgA) ----
    fused_agg_gemm_kernel<32, 16><<<(N + 63) / 64, 256>>>(b2, W3, N, 1);

    // ---- fused: agg(16) + pooling partials (reads msgA) ----
    int nbPool = (N + 127) / 128;
    fused_agg_pool_kernel<<<nbPool, 256>>>(b3, N);

    // ---- head ----
    final_mlp_kernel<<<1, 32>>>(Wf, bf, Ws, bs, (float*)d_out, N, nbPool);
}